// round 15
// baseline (speedup 1.0000x reference)
#include <cuda_runtime.h>
#include <cuda_bf16.h>

// P_TNCN: 512-step temporal predictive-coding recurrence.
// 8 groups x 16 CTAs; each group owns 16 batch elements; each CTA owns a
// weight slice (32 states of w_r/w_f, 16 outputs of w_o) resident in SMEM.
// Activations exchanged through L2 scratch with per-group atomic barriers.

#define SEQ   512
#define BATCH 128
#define SDIM  512
#define ODIM  256
#define NG    8      // groups
#define NC    16     // CTAs per group
#define BG    16     // batch per group
#define SSL   32     // states per CTA
#define OSL   16     // output dims per CTA
#define NTHR  256

#define INV_TAU 0.5f
#define ALPHA   0.01f
#define BETA    0.5f

// Exchange scratch, [k][batch] layout for conflict-free SMEM staging.
__device__ __align__(16) float g_th [NG][SDIM][BG];
__device__ __align__(16) float g_thp[NG][SDIM][BG];
__device__ __align__(16) float g_err[NG][ODIM][BG];
__device__ int g_cnt[NG];

__global__ void tncn_init() {
    if (threadIdx.x < NG) g_cnt[threadIdx.x] = 0;
}

struct __align__(16) Smem {
    float wr[SDIM][SSL];    // wr[k][j]  = w_r[S0+j][k]   (64 KB)
    float wo[SDIM][OSL];    // wo[k][j]  = w_o[O0+j][k]   (32 KB)
    float wf[ODIM][SSL];    // wf[o][j]  = w_f[S0+j][o]   (32 KB)
    float act[SDIM][BG];    // staged tanh(h) / tanh(hp)  (32 KB)
    float errs[ODIM][BG];   // staged error               (16 KB)
    float br[SSL];
    float bo[OSL];
};

// Monotonic-counter barrier among the NC CTAs of one group.
// __syncthreads() orders all threads' prior writes before thread 0's
// gpu-scope release; readers re-load scratch with __ldcg (L1 bypass).
__device__ __forceinline__ void group_barrier(int grp, int target) {
    __syncthreads();
    if (threadIdx.x == 0) {
        __threadfence();                       // release all CTA writes
        atomicAdd(&g_cnt[grp], 1);
        int v;
        do {
            asm volatile("ld.acquire.gpu.b32 %0, [%1];"
                         : "=r"(v) : "l"(&g_cnt[grp]) : "memory");
        } while (v < target);
    }
    __syncthreads();
}

__device__ __forceinline__ void stage16(float* dst, const float* src, int n4) {
    float4*       d = reinterpret_cast<float4*>(dst);
    const float4* s = reinterpret_cast<const float4*>(src);
    for (int i = threadIdx.x; i < n4; i += NTHR) d[i] = __ldcg(s + i);
}

__global__ void __launch_bounds__(NTHR, 1) tncn_kernel(
    const float* __restrict__ x,
    const float* __restrict__ h_init,
    const float* __restrict__ w_o,
    const float* __restrict__ b_o,
    const float* __restrict__ w_r,
    const float* __restrict__ b_r,
    const float* __restrict__ w_f,
    float* __restrict__ out)
{
    extern __shared__ char smraw[];
    Smem* sm = reinterpret_cast<Smem*>(smraw);

    const int tid = threadIdx.x;
    const int grp = blockIdx.x / NC;
    const int r   = blockIdx.x % NC;
    const int B0 = grp * BG;
    const int S0 = r * SSL;
    const int O0 = r * OSL;

    // One-time weight load (transposed to k-major). Slow STS pattern is fine:
    // amortized over 512 steps.
    for (int idx = tid; idx < SSL * SDIM; idx += NTHR) {
        int j = idx >> 9, k = idx & (SDIM - 1);
        sm->wr[k][j] = w_r[(S0 + j) * SDIM + k];
    }
    for (int idx = tid; idx < OSL * SDIM; idx += NTHR) {
        int j = idx >> 9, k = idx & (SDIM - 1);
        sm->wo[k][j] = w_o[(O0 + j) * SDIM + k];
    }
    for (int idx = tid; idx < SSL * ODIM; idx += NTHR) {
        int j = idx >> 8, k = idx & (ODIM - 1);
        sm->wf[k][j] = w_f[(S0 + j) * ODIM + k];
    }
    if (tid < SSL) sm->br[tid] = b_r[S0 + tid];
    if (tid < OSL) sm->bo[tid] = b_o[O0 + tid];

    // Per-thread hidden-state ownership: (b, j0..j0+1). Same thread owns the
    // same pair across P1/P2/P4, so h and h_prior live in registers.
    const int b  = tid >> 4;            // 0..15
    const int j0 = (tid & 15) * 2;      // 0,2,...,30
    float h0 = h_init[(B0 + b) * SDIM + S0 + j0];
    float h1 = h_init[(B0 + b) * SDIM + S0 + j0 + 1];

    __syncthreads();

    int tgt = 0;
    for (int t = 0; t < SEQ; t++) {
        // ---- P1: publish tanh(h_post_old) slice ----
        g_th[grp][S0 + j0][b]     = tanhf(h0);
        g_th[grp][S0 + j0 + 1][b] = tanhf(h1);
        tgt += NC; group_barrier(grp, tgt);

        // ---- P2: h_prior = 0.5*h + 0.5*(th @ w_r^T + b_r) ----
        stage16(&sm->act[0][0], &g_th[grp][0][0], SDIM * BG / 4);
        __syncthreads();

        float a0 = 0.f, a1 = 0.f;
        #pragma unroll 8
        for (int k = 0; k < SDIM; k++) {
            const float  xv = sm->act[k][b];                       // broadcast
            const float2 w  = *(const float2*)&sm->wr[k][j0];      // conflict-free
            a0 = fmaf(w.x, xv, a0);
            a1 = fmaf(w.y, xv, a1);
        }
        const float hp0 = (1.f - INV_TAU) * h0 + INV_TAU * (a0 + sm->br[j0]);
        const float hp1 = (1.f - INV_TAU) * h1 + INV_TAU * (a1 + sm->br[j0 + 1]);
        g_thp[grp][S0 + j0][b]     = tanhf(hp0);
        g_thp[grp][S0 + j0 + 1][b] = tanhf(hp1);
        tgt += NC; group_barrier(grp, tgt);

        // ---- P3: x_pred = thp @ w_o^T + b_o ; error = x_pred - x[t] ----
        stage16(&sm->act[0][0], &g_thp[grp][0][0], SDIM * BG / 4);
        __syncthreads();

        if (tid < 128) {
            const int bb = tid >> 3;           // 0..15
            const int o0 = (tid & 7) * 2;      // 0,2,...,14
            float p0 = sm->bo[o0], p1 = sm->bo[o0 + 1];
            #pragma unroll 8
            for (int k = 0; k < SDIM; k++) {
                const float  xv = sm->act[k][bb];
                const float2 w  = *(const float2*)&sm->wo[k][o0];
                p0 = fmaf(w.x, xv, p0);
                p1 = fmaf(w.y, xv, p1);
            }
            const size_t base = (size_t)t * (BATCH * ODIM)
                              + (size_t)(B0 + bb) * ODIM + (O0 + o0);
            const float2 xin = *(const float2*)&x[base];
            const float e0 = p0 - xin.x;
            const float e1 = p1 - xin.y;
            *(float2*)&out[base] = make_float2(e0, e1);     // kernel output
            g_err[grp][O0 + o0][bb]     = e0;               // exchange copy
            g_err[grp][O0 + o0 + 1][bb] = e1;
        }
        tgt += NC; group_barrier(grp, tgt);

        // ---- P4: h_post = hp - alpha*sign(hp) - beta*(err @ w_f^T) ----
        stage16(&sm->errs[0][0], &g_err[grp][0][0], ODIM * BG / 4);
        __syncthreads();

        float c0 = 0.f, c1 = 0.f;
        #pragma unroll 8
        for (int k = 0; k < ODIM; k++) {
            const float  ev = sm->errs[k][b];
            const float2 w  = *(const float2*)&sm->wf[k][j0];
            c0 = fmaf(w.x, ev, c0);
            c1 = fmaf(w.y, ev, c1);
        }
        const float s0 = (hp0 > 0.f) ? 1.f : ((hp0 < 0.f) ? -1.f : 0.f);
        const float s1 = (hp1 > 0.f) ? 1.f : ((hp1 < 0.f) ? -1.f : 0.f);
        h0 = hp0 - ALPHA * s0 - BETA * c0;
        h1 = hp1 - ALPHA * s1 - BETA * c1;
    }
}

extern "C" void kernel_launch(void* const* d_in, const int* in_sizes, int n_in,
                              void* d_out, int out_size) {
    const float* x      = (const float*)d_in[0];
    const float* h_init = (const float*)d_in[1];
    const float* w_o    = (const float*)d_in[2];
    const float* b_o    = (const float*)d_in[3];
    const float* w_r    = (const float*)d_in[4];
    const float* b_r    = (const float*)d_in[5];
    const float* w_f    = (const float*)d_in[6];
    // d_in[7] = w_i: mathematically unused (reference multiplies it by zeros).
    float* out = (float*)d_out;

    cudaFuncSetAttribute(tncn_kernel,
                         cudaFuncAttributeMaxDynamicSharedMemorySize,
                         (int)sizeof(Smem));

    tncn_init<<<1, 32>>>();   // reset group barrier counters every replay
    tncn_kernel<<<NG * NC, NTHR, sizeof(Smem)>>>(
        x, h_init, w_o, b_o, w_r, b_r, w_f, out);
}

// round 16
// speedup vs baseline: 1.0469x; 1.0469x over previous
#include <cuda_runtime.h>
#include <cuda_bf16.h>

// P_TNCN: 512-step temporal predictive-coding recurrence.
// 8 groups x 16 CTAs; group owns 16 batch elems; CTA owns a weight slice
// (32 states of w_r/w_f, 16 outputs of w_o) resident in SMEM.
// R15: 2x2 register tiles + split-K, packed fma.rn.f32x2, flag barriers.

#define SEQ   512
#define BATCH 128
#define SDIM  512
#define ODIM  256
#define NG    8      // groups
#define NC    16     // CTAs per group
#define BG    16     // batch per group
#define SSL   32     // states per CTA
#define OSL   16     // output dims per CTA
#define NTHR  256

#define INV_TAU 0.5f
#define ALPHA   0.01f
#define BETA    0.5f

typedef unsigned long long u64;

// Exchange scratch, [k][batch] layout (rows of 64B, float2-friendly).
__device__ __align__(16) float g_th [NG][SDIM][BG];
__device__ __align__(16) float g_thp[NG][SDIM][BG];
__device__ __align__(16) float g_err[NG][ODIM][BG];
__device__ int g_flag[NG][NC];

__global__ void tncn_init() {
    int i = threadIdx.x;
    if (i < NG * NC) ((int*)g_flag)[i] = 0;
}

struct __align__(16) Smem {
    float wr[SDIM][SSL];    // wr[k][j] = w_r[S0+j][k]   64 KB
    float wo[SDIM][OSL];    // wo[k][j] = w_o[O0+j][k]   32 KB
    float wf[ODIM][SSL];    // wf[o][j] = w_f[S0+j][o]   32 KB
    float act[SDIM][BG];    // staged tanh(h) / tanh(hp) 32 KB
    float errs[ODIM][BG];   // staged error              16 KB
    u64   red[384];         // split-K partial sums       3 KB
    float br[SSL];
    float bo[OSL];
};

// ---- packed-f32 helpers (FFMA2 exists only via PTX fma.rn.f32x2) ----
__device__ __forceinline__ void fma2(u64& acc, u64 w, u64 a) {
    asm("fma.rn.f32x2 %0, %1, %2, %0;" : "+l"(acc) : "l"(w), "l"(a));
}
__device__ __forceinline__ void add2(u64& a, u64 b) {
    asm("add.rn.f32x2 %0, %0, %1;" : "+l"(a) : "l"(b));
}
__device__ __forceinline__ u64 splat2(float v) {
    u64 r;
    asm("mov.b64 %0, {%1, %1};" : "=l"(r) : "f"(v));
    return r;
}
__device__ __forceinline__ void unpack2(u64 v, float& lo, float& hi) {
    asm("mov.b64 {%0, %1}, %2;" : "=f"(lo), "=f"(hi) : "l"(v));
}
__device__ __forceinline__ float sgn(float v) {
    return (v > 0.f) ? 1.f : ((v < 0.f) ? -1.f : 0.f);
}

// Flag barrier: per-CTA release flags, 16 parallel pollers. No atomic
// contention (the old 16-way atomicAdd to one address serialized ~32cyc each).
__device__ __forceinline__ void group_barrier(const int grp, const int r, const int ph) {
    __syncthreads();
    if (threadIdx.x == 0) {
        __threadfence();   // order all CTA threads' prior STGs (post-bar)
        asm volatile("st.release.gpu.b32 [%0], %1;"
                     :: "l"(&g_flag[grp][r]), "r"(ph) : "memory");
    }
    if (threadIdx.x < NC) {
        const int* p = &g_flag[grp][threadIdx.x];
        int v;
        do {
            asm volatile("ld.acquire.gpu.b32 %0, [%1];"
                         : "=r"(v) : "l"(p) : "memory");
        } while (v < ph);
    }
    __syncthreads();
}

__device__ __forceinline__ void stage16(float* dst, const float* src, int n4) {
    float4*       d = reinterpret_cast<float4*>(dst);
    const float4* s = reinterpret_cast<const float4*>(src);
    for (int i = threadIdx.x; i < n4; i += NTHR) d[i] = __ldcg(s + i);
}

__global__ void __launch_bounds__(NTHR, 1) tncn_kernel(
    const float* __restrict__ x,
    const float* __restrict__ h_init,
    const float* __restrict__ w_o,
    const float* __restrict__ b_o,
    const float* __restrict__ w_r,
    const float* __restrict__ b_r,
    const float* __restrict__ w_f,
    float* __restrict__ out)
{
    extern __shared__ char smraw[];
    Smem* sm = reinterpret_cast<Smem*>(smraw);

    const int tid = threadIdx.x;
    const int grp = blockIdx.x / NC;
    const int r   = blockIdx.x % NC;
    const int B0 = grp * BG;
    const int S0 = r * SSL;
    const int O0 = r * OSL;

    // One-time weight load (k-major). Amortized over 512 steps.
    for (int idx = tid; idx < SSL * SDIM; idx += NTHR) {
        int j = idx >> 9, k = idx & (SDIM - 1);
        sm->wr[k][j] = w_r[(S0 + j) * SDIM + k];
    }
    for (int idx = tid; idx < OSL * SDIM; idx += NTHR) {
        int j = idx >> 9, k = idx & (SDIM - 1);
        sm->wo[k][j] = w_o[(O0 + j) * SDIM + k];
    }
    for (int idx = tid; idx < SSL * ODIM; idx += NTHR) {
        int j = idx >> 8, k = idx & (ODIM - 1);
        sm->wf[k][j] = w_f[(S0 + j) * ODIM + k];
    }
    if (tid < SSL) sm->br[tid] = b_r[S0 + tid];
    if (tid < OSL) sm->bo[tid] = b_o[O0 + tid];

    // ---- thread tilings ----
    // P2/P4: 2 k-halves x (16 j-pairs x 8 b-pairs); thread owns 2j x 2b.
    const int kh = tid >> 7;                // 0/1
    const int u  = tid & 127;
    const int j0 = (u & 15) * 2;            // 0,2,...,30
    const int b0 = (u >> 4) * 2;            // 0,2,...,14
    // P3: 4 k-quarters x (8 o-pairs x 8 b-pairs); thread owns 2o x 2b.
    const int kq  = tid >> 6;               // 0..3
    const int u3  = tid & 63;
    const int o0  = (u3 & 7) * 2;           // 0,2,...,14
    const int bq0 = (u3 >> 3) * 2;          // 0,2,...,14

    // Hidden state registers: h[j][b], owned by kh==0 threads.
    float h00 = 0.f, h01 = 0.f, h10 = 0.f, h11 = 0.f;
    if (kh == 0) {
        h00 = h_init[(B0 + b0)     * SDIM + S0 + j0];
        h01 = h_init[(B0 + b0 + 1) * SDIM + S0 + j0];
        h10 = h_init[(B0 + b0)     * SDIM + S0 + j0 + 1];
        h11 = h_init[(B0 + b0 + 1) * SDIM + S0 + j0 + 1];
    }
    float hp00 = 0.f, hp01 = 0.f, hp10 = 0.f, hp11 = 0.f;

    __syncthreads();

    int ph = 0;
    for (int t = 0; t < SEQ; t++) {
        // Prefetch x[t] for P3 (hidden behind P1 barrier + P2 compute).
        float2 xf0 = make_float2(0.f, 0.f), xf1 = xf0;
        if (kq == 0) {
            const float* xb = x + (size_t)t * (BATCH * ODIM)
                                + (size_t)(B0 + bq0) * ODIM + (O0 + o0);
            xf0 = *(const float2*)xb;
            xf1 = *(const float2*)(xb + ODIM);
        }

        // ---- P1: publish tanh(h_post_old) slice ----
        if (kh == 0) {
            *(float2*)&g_th[grp][S0 + j0][b0] =
                make_float2(tanhf(h00), tanhf(h01));
            *(float2*)&g_th[grp][S0 + j0 + 1][b0] =
                make_float2(tanhf(h10), tanhf(h11));
        }
        ph++; group_barrier(grp, r, ph);

        // ---- P2: h_prior = 0.5*h + 0.5*(th @ w_r^T + b_r) ----
        stage16(&sm->act[0][0], &g_th[grp][0][0], SDIM * BG / 4);
        __syncthreads();

        u64 ab0 = 0, ab1 = 0;           // pack along j: {j0, j1}
        {
            const int kbase = kh << 8;
            #pragma unroll 8
            for (int kk = 0; kk < 256; kk++) {
                const int k = kbase + kk;
                const u64    w2 = *(const u64*)&sm->wr[k][j0];
                const float2 a2 = *(const float2*)&sm->act[k][b0];
                fma2(ab0, w2, splat2(a2.x));
                fma2(ab1, w2, splat2(a2.y));
            }
        }
        if (kh == 1) { sm->red[u * 2] = ab0; sm->red[u * 2 + 1] = ab1; }
        __syncthreads();
        if (kh == 0) {
            add2(ab0, sm->red[u * 2]);
            add2(ab1, sm->red[u * 2 + 1]);
            float a0j0, a0j1, a1j0, a1j1;
            unpack2(ab0, a0j0, a0j1);   // batch b0
            unpack2(ab1, a1j0, a1j1);   // batch b0+1
            const float brj0 = sm->br[j0], brj1 = sm->br[j0 + 1];
            hp00 = (1.f - INV_TAU) * h00 + INV_TAU * (a0j0 + brj0);
            hp01 = (1.f - INV_TAU) * h01 + INV_TAU * (a1j0 + brj0);
            hp10 = (1.f - INV_TAU) * h10 + INV_TAU * (a0j1 + brj1);
            hp11 = (1.f - INV_TAU) * h11 + INV_TAU * (a1j1 + brj1);
            *(float2*)&g_thp[grp][S0 + j0][b0] =
                make_float2(tanhf(hp00), tanhf(hp01));
            *(float2*)&g_thp[grp][S0 + j0 + 1][b0] =
                make_float2(tanhf(hp10), tanhf(hp11));
        }
        ph++; group_barrier(grp, r, ph);

        // ---- P3: x_pred = thp @ w_o^T + b_o ; error = x_pred - x[t] ----
        stage16(&sm->act[0][0], &g_thp[grp][0][0], SDIM * BG / 4);
        __syncthreads();

        u64 pb0 = 0, pb1 = 0;           // pack along o: {o0, o1}
        {
            const int kbase3 = kq << 7;
            #pragma unroll 8
            for (int kk = 0; kk < 128; kk++) {
                const int k = kbase3 + kk;
                const u64    w2 = *(const u64*)&sm->wo[k][o0];
                const float2 a2 = *(const float2*)&sm->act[k][bq0];
                fma2(pb0, w2, splat2(a2.x));
                fma2(pb1, w2, splat2(a2.y));
            }
        }
        if (kq != 0) {
            sm->red[((kq - 1) * 64 + u3) * 2]     = pb0;
            sm->red[((kq - 1) * 64 + u3) * 2 + 1] = pb1;
        }
        __syncthreads();
        if (kq == 0) {
            #pragma unroll
            for (int q = 0; q < 3; q++) {
                add2(pb0, sm->red[(q * 64 + u3) * 2]);
                add2(pb1, sm->red[(q * 64 + u3) * 2 + 1]);
            }
            float p00, p01, p10, p11;
            unpack2(pb0, p00, p01);     // batch bq0:   o0, o1
            unpack2(pb1, p10, p11);     // batch bq0+1: o0, o1
            const float bo0 = sm->bo[o0], bo1 = sm->bo[o0 + 1];
            const float e00 = p00 + bo0 - xf0.x;
            const float e01 = p01 + bo1 - xf0.y;
            const float e10 = p10 + bo0 - xf1.x;
            const float e11 = p11 + bo1 - xf1.y;
            const size_t base = (size_t)t * (BATCH * ODIM)
                              + (size_t)(B0 + bq0) * ODIM + (O0 + o0);
            *(float2*)&out[base]        = make_float2(e00, e01);
            *(float2*)&out[base + ODIM] = make_float2(e10, e11);
            // exchange copy, [o][b] layout: (b,b+1) adjacent per o-row
            *(float2*)&g_err[grp][O0 + o0][bq0]     = make_float2(e00, e10);
            *(float2*)&g_err[grp][O0 + o0 + 1][bq0] = make_float2(e01, e11);
        }
        ph++; group_barrier(grp, r, ph);

        // ---- P4: h_post = hp - alpha*sign(hp) - beta*(err @ w_f^T) ----
        stage16(&sm->errs[0][0], &g_err[grp][0][0], ODIM * BG / 4);
        __syncthreads();

        u64 cb0 = 0, cb1 = 0;           // pack along j: {j0, j1}
        {
            const int kbase4 = kh << 7;
            #pragma unroll 8
            for (int kk = 0; kk < 128; kk++) {
                const int k = kbase4 + kk;
                const u64    w2 = *(const u64*)&sm->wf[k][j0];
                const float2 a2 = *(const float2*)&sm->errs[k][b0];
                fma2(cb0, w2, splat2(a2.x));
                fma2(cb1, w2, splat2(a2.y));
            }
        }
        if (kh == 1) { sm->red[u * 2] = cb0; sm->red[u * 2 + 1] = cb1; }
        __syncthreads();
        if (kh == 0) {
            add2(cb0, sm->red[u * 2]);
            add2(cb1, sm->red[u * 2 + 1]);
            float c00, c01, c10, c11;
            unpack2(cb0, c00, c01);     // batch b0:   j0, j1
            unpack2(cb1, c10, c11);     // batch b0+1: j0, j1
            h00 = hp00 - ALPHA * sgn(hp00) - BETA * c00;
            h10 = hp10 - ALPHA * sgn(hp10) - BETA * c01;
            h01 = hp01 - ALPHA * sgn(hp01) - BETA * c10;
            h11 = hp11 - ALPHA * sgn(hp11) - BETA * c11;
        }
        // No extra barrier: peers finished reading g_th before their b2,
        // which precedes our b3; safe to republish g_th next iteration.
    }
}

extern "C" void kernel_launch(void* const* d_in, const int* in_sizes, int n_in,
                              void* d_out, int out_size) {
    const float* x      = (const float*)d_in[0];
    const float* h_init = (const float*)d_in[1];
    const float* w_o    = (const float*)d_in[2];
    const float* b_o    = (const float*)d_in[3];
    const float* w_r    = (const float*)d_in[4];
    const float* b_r    = (const float*)d_in[5];
    const float* w_f    = (const float*)d_in[6];
    // d_in[7] = w_i: mathematically unused (reference multiplies it by zeros).
    float* out = (float*)d_out;

    cudaFuncSetAttribute(tncn_kernel,
                         cudaFuncAttributeMaxDynamicSharedMemorySize,
                         (int)sizeof(Smem));

    tncn_init<<<1, 128>>>();   // reset barrier flags every replay
    tncn_kernel<<<NG * NC, NTHR, sizeof(Smem)>>>(
        x, h_init, w_o, b_o, w_r, b_r, w_f, out);
}